// round 16
// baseline (speedup 1.0000x reference)
#include <cuda_runtime.h>
#include <cuda_bf16.h>

// InverseLeakySoftplus: solve a*x + (1-a)*softplus(x) = y, a = 0.1+0.4*sigmoid(raw_alpha).
//
// R15 post-mortem: main pinned at ~47us by the ~58% DRAM ceiling for a
// 50/50 R/W stream; total-main gap ~5-6us = builder launch + replay overhead.
// R16: (a) software-pipelined double buffer — next tile's loads issued BEFORE
// current tile's stores (longer read runs, store drain overlapped);
// (b) builder halved: one Newton solve/thread writes x only, main computes
// deltas from adjacent (coalesced, L2-hot) reads during the smem fill.

#define NSEG  3200
#define YMINF (-16.0f)
#define H_F   0.01f
#define INVH  100.0f
#define TOFF  1600.0f          // -YMIN/h
#define TPB   256
#define IPT   4                // float4 per thread per tile
#define TILE  (TPB * IPT)      // 1024 float4 per block-tile
#define NBLOCKS 608            // 152 SMs x 4 blocks

__device__ float g_x[NSEG + 1];   // x(y_k) knots
__device__ float g_inva;

// ---------- table builder: ONE knot per thread ----------
__global__ void build_table(const float* __restrict__ raw_alpha)
{
    int k = blockIdx.x * blockDim.x + threadIdx.x;
    float r    = __ldg(raw_alpha);
    float sig  = __fdividef(1.0f, 1.0f + __expf(-r));
    float a    = fmaf(0.4f, sig, 0.1f);
    float oma  = 1.0f - a;
    float inva = __fdividef(1.0f, a);
    if (k == 0) g_inva = inva;
    if (k <= NSEG) {
        float y = YMINF + (float)k * H_F;
        float x = (y > 0.0f) ? y : y * inva;
#pragma unroll
        for (int it = 0; it < 6; ++it) {
            float e  = __expf(-fabsf(x));
            float op = 1.0f + e;
            float sp = __logf(op) + fmaxf(x, 0.0f);
            float fx = fmaf(a, x, oma * sp);
            float num = (x >= 0.0f) ? fmaf(a, e, 1.0f) : (a + e);
            x -= __fdividef((fx - y) * op, num);
        }
        g_x[k] = x;
    }
}

// ---------- main: lerp, one LDS.64 per element, zero MUFU ----------
__device__ __forceinline__ float lerp_solve(float y, float inva,
                                            const float2* __restrict__ s_tab)
{
    float t = fmaf(y, INVH, TOFF);
    t = fminf(fmaxf(t, 0.0f), (float)NSEG - 0.001f);
    int   k  = (int)t;
    float fr = t - (float)k;
    float2 p = s_tab[k];
    float x  = fmaf(fr, p.y, p.x);
    x = (y >=  16.0f) ? y        : x;
    x = (y <= -16.0f) ? y * inva : x;
    return x;
}

__device__ __forceinline__ void fill_table(float2* s_tab)
{
    for (int j = threadIdx.x; j < NSEG; j += TPB) {
        float x0 = g_x[j];
        float x1 = g_x[j + 1];               // coalesced, L2-hot
        s_tab[j] = make_float2(x0, x1 - x0);
    }
}

__device__ __forceinline__ void compute_store(const float4* v, float4* __restrict__ out,
                                              long long i0, float inva,
                                              const float2* __restrict__ s_tab)
{
#pragma unroll
    for (int j = 0; j < IPT; ++j) {
        float4 rr;
        rr.x = lerp_solve(v[j].x, inva, s_tab);
        rr.y = lerp_solve(v[j].y, inva, s_tab);
        rr.z = lerp_solve(v[j].z, inva, s_tab);
        rr.w = lerp_solve(v[j].w, inva, s_tab);
        out[i0 + j * TPB] = rr;
    }
}

// Predicate-free, software-pipelined: requires n4 % TILE == 0.
__global__ void __launch_bounds__(TPB, 4)
inv_lsp_main_exact(const float4* __restrict__ in, float4* __restrict__ out, int n4)
{
    __shared__ float2 s_tab[NSEG];
    fill_table(s_tab);
    float inva = g_inva;
    __syncthreads();

    long long base = (long long)blockIdx.x * TILE + threadIdx.x;
    long long step = (long long)gridDim.x * TILE;

    float4 v[IPT];
#pragma unroll
    for (int j = 0; j < IPT; ++j)               // prologue loads
        v[j] = in[base + j * TPB];

    long long i0 = base;
    for (long long i1 = base + step; i1 < n4; i1 += step) {
        float4 vn[IPT];
#pragma unroll
        for (int j = 0; j < IPT; ++j)           // NEXT tile loads BEFORE stores
            vn[j] = in[i1 + j * TPB];
        compute_store(v, out, i0, inva, s_tab); // current tile compute+store
#pragma unroll
        for (int j = 0; j < IPT; ++j) v[j] = vn[j];
        i0 = i1;
    }
    compute_store(v, out, i0, inva, s_tab);     // epilogue
}

// Guarded fallback (general n4), non-pipelined.
__global__ void __launch_bounds__(TPB, 4)
inv_lsp_main_guard(const float4* __restrict__ in, float4* __restrict__ out, int n4)
{
    __shared__ float2 s_tab[NSEG];
    fill_table(s_tab);
    float inva = g_inva;
    __syncthreads();

    long long base = (long long)blockIdx.x * TILE + threadIdx.x;
    long long step = (long long)gridDim.x * TILE;

    for (long long i0 = base; i0 < n4; i0 += step) {
        float4 v[IPT];
        int    ok[IPT];
#pragma unroll
        for (int j = 0; j < IPT; ++j) {
            long long i = i0 + j * TPB;
            ok[j] = (i < n4);
            if (ok[j]) v[j] = in[i];
        }
#pragma unroll
        for (int j = 0; j < IPT; ++j) {
            if (ok[j]) {
                float4 rr;
                rr.x = lerp_solve(v[j].x, inva, s_tab);
                rr.y = lerp_solve(v[j].y, inva, s_tab);
                rr.z = lerp_solve(v[j].z, inva, s_tab);
                rr.w = lerp_solve(v[j].w, inva, s_tab);
                out[i0 + j * TPB] = rr;
            }
        }
    }
}

// ---------- scalar tail (safety; unused when n % 4 == 0) ----------
__global__ void inv_lsp_scalar_tail(const float* __restrict__ in,
                                    float* __restrict__ out,
                                    int start, int n)
{
    int i = start + blockIdx.x * blockDim.x + threadIdx.x;
    if (i >= n) return;
    float inva = g_inva;
    float a    = __fdividef(1.0f, inva);
    float oma  = 1.0f - a;
    float y = in[i];
    float x = (y > 0.0f) ? y : y * inva;
#pragma unroll
    for (int it = 0; it < 8; ++it) {
        float e  = __expf(-fabsf(x));
        float op = 1.0f + e;
        float sp = __logf(op) + fmaxf(x, 0.0f);
        float fx = fmaf(a, x, oma * sp);
        float num = (x >= 0.0f) ? fmaf(a, e, 1.0f) : (a + e);
        x -= __fdividef((fx - y) * op, num);
    }
    out[i] = x;
}

extern "C" void kernel_launch(void* const* d_in, const int* in_sizes, int n_in,
                              void* d_out, int out_size)
{
    const float* in        = (const float*)d_in[0];
    const float* raw_alpha = (const float*)d_in[1];
    float* out             = (float*)d_out;
    int n = in_sizes[0];

    build_table<<<(NSEG + 128) / 128, 128>>>(raw_alpha);

    int n4 = n / 4;
    if (n4 > 0) {
        int blocks = NBLOCKS;
        long long needed = ((long long)n4 + TPB - 1) / TPB;
        if (needed < blocks) blocks = (int)needed;
        if ((n4 % TILE) == 0 && n4 / TILE >= 1)
            inv_lsp_main_exact<<<blocks, TPB>>>((const float4*)in, (float4*)out, n4);
        else
            inv_lsp_main_guard<<<blocks, TPB>>>((const float4*)in, (float4*)out, n4);
    }
    int rem = n - n4 * 4;
    if (rem > 0) {
        inv_lsp_scalar_tail<<<1, 256>>>(in, out, n4 * 4, n);
    }
}